// round 1
// baseline (speedup 1.0000x reference)
#include <cuda_runtime.h>
#include <math.h>

#define B_  2
#define T_  2048
#define D_  2048
#define H_  32
#define HD_ 64
#define M_  (B_ * T_)          // 4096 rows for all GEMMs

// ---------------------------------------------------------------------------
// Scratch (device globals — no allocation allowed)
// ---------------------------------------------------------------------------
__device__ float g_q[(size_t)B_ * H_ * T_ * HD_];   // [bh][t][hd]
__device__ float g_k[(size_t)B_ * H_ * T_ * HD_];
__device__ float g_v[(size_t)B_ * H_ * T_ * HD_];
__device__ float g_ctx[(size_t)M_ * D_];            // [b*T+t][h*HD+hd]

// ---------------------------------------------------------------------------
// GEMM: C[m][n] = sum_k A[m][k] * W[n][k] + bias[n]
// A: [M_, 2048] row-major, W: [2048, 2048] row-major (NT layout).
// SPLIT_HEADS=1: write to out[((b*H+h)*T + t)*HD + hd]  (head-split for attn)
// SPLIT_HEADS=0: write to out[m*D + n]
// BM=BN=128, BK=16, 256 threads, 8x8 per thread.
// ---------------------------------------------------------------------------
template <int SPLIT_HEADS>
__global__ __launch_bounds__(256, 2) void gemm_nt(
    const float* __restrict__ A,
    const float* __restrict__ W,
    const float* __restrict__ bias,
    float* __restrict__ out)
{
    __shared__ float As[16][128];   // As[k][m]
    __shared__ float Bs[16][128];   // Bs[k][n]

    const int tid = threadIdx.x;
    const int tx  = tid & 15;       // 0..15 -> col group
    const int ty  = tid >> 4;       // 0..15 -> row group
    const int m0  = blockIdx.y * 128;
    const int n0  = blockIdx.x * 128;

    float acc[8][8];
#pragma unroll
    for (int i = 0; i < 8; i++)
#pragma unroll
        for (int j = 0; j < 8; j++) acc[i][j] = 0.0f;

    for (int k0 = 0; k0 < 2048; k0 += 16) {
        // Load 128x16 A-tile and 128x16 W-tile (each 512 float4, 2/thread)
#pragma unroll
        for (int it = 0; it < 2; it++) {
            int idx = tid + it * 256;         // 0..511
            int r   = idx >> 2;               // 0..127
            int c   = (idx & 3) * 4;          // 0,4,8,12
            float4 a = *reinterpret_cast<const float4*>(
                &A[(size_t)(m0 + r) * 2048 + k0 + c]);
            As[c + 0][r] = a.x; As[c + 1][r] = a.y;
            As[c + 2][r] = a.z; As[c + 3][r] = a.w;
            float4 b = *reinterpret_cast<const float4*>(
                &W[(size_t)(n0 + r) * 2048 + k0 + c]);
            Bs[c + 0][r] = b.x; Bs[c + 1][r] = b.y;
            Bs[c + 2][r] = b.z; Bs[c + 3][r] = b.w;
        }
        __syncthreads();

#pragma unroll
        for (int k = 0; k < 16; k++) {
            float a[8], b[8];
            *reinterpret_cast<float4*>(&a[0]) =
                *reinterpret_cast<const float4*>(&As[k][ty * 8]);
            *reinterpret_cast<float4*>(&a[4]) =
                *reinterpret_cast<const float4*>(&As[k][ty * 8 + 4]);
            *reinterpret_cast<float4*>(&b[0]) =
                *reinterpret_cast<const float4*>(&Bs[k][tx * 8]);
            *reinterpret_cast<float4*>(&b[4]) =
                *reinterpret_cast<const float4*>(&Bs[k][tx * 8 + 4]);
#pragma unroll
            for (int i = 0; i < 8; i++)
#pragma unroll
                for (int j = 0; j < 8; j++)
                    acc[i][j] = fmaf(a[i], b[j], acc[i][j]);
        }
        __syncthreads();
    }

    // Epilogue: add bias, write
    float bv[8];
#pragma unroll
    for (int j = 0; j < 8; j++) bv[j] = bias[n0 + tx * 8 + j];

#pragma unroll
    for (int i = 0; i < 8; i++) {
        int m = m0 + ty * 8 + i;
#pragma unroll
        for (int j = 0; j < 8; j++) {
            int n = n0 + tx * 8 + j;
            float v = acc[i][j] + bv[j];
            if (SPLIT_HEADS) {
                int b  = m >> 11;       // m / T_
                int t  = m & (T_ - 1);
                int h  = n >> 6;        // n / HD_
                int hd = n & (HD_ - 1);
                out[(((size_t)(b * H_ + h)) * T_ + t) * HD_ + hd] = v;
            } else {
                out[(size_t)m * D_ + n] = v;
            }
        }
    }
}

// ---------------------------------------------------------------------------
// Flash attention (causal), fp32.
// Grid: (T/64, B*H).  Block: 256 threads (16x16).
// Br = Bc = 64, HD = 64. Per-thread: 4 query rows (4*ty+i), 4 cols (tx+16*j).
// Writes ctx in [b*T+t][h*HD+hd] layout (plain GEMM input for O-proj).
// ---------------------------------------------------------------------------
#define FA_S 68   // padded smem row stride (floats); 68*4B keeps float4 align

__global__ __launch_bounds__(256, 3) void flash_attn(
    const float* __restrict__ gq,
    const float* __restrict__ gk,
    const float* __restrict__ gv,
    float* __restrict__ gctx)
{
    extern __shared__ float smem[];
    float* sQ = smem;                 // 64 x FA_S
    float* sK = sQ + 64 * FA_S;
    float* sV = sK + 64 * FA_S;
    float* sP = sV + 64 * FA_S;

    const int tid = threadIdx.x;
    const int tx  = tid & 15;
    const int ty  = tid >> 4;
    const int bh  = blockIdx.y;               // b*H + h
    const int q0  = blockIdx.x * 64;

    const float* Qg = gq + (size_t)bh * T_ * HD_;
    const float* Kg = gk + (size_t)bh * T_ * HD_;
    const float* Vg = gv + (size_t)bh * T_ * HD_;

    // Load Q tile (64x64): 1024 float4, 4 per thread
#pragma unroll
    for (int it = 0; it < 4; it++) {
        int idx = tid + it * 256;   // 0..1023
        int r = idx >> 4;           // 0..63
        int c = (idx & 15) * 4;     // 0..60
        float4 v = *reinterpret_cast<const float4*>(&Qg[(size_t)(q0 + r) * HD_ + c]);
        *reinterpret_cast<float4*>(&sQ[r * FA_S + c]) = v;
    }

    float o[4][4];
    float mrow[4], lrow[4];
#pragma unroll
    for (int i = 0; i < 4; i++) {
        mrow[i] = -1e30f; lrow[i] = 0.0f;
#pragma unroll
        for (int j = 0; j < 4; j++) o[i][j] = 0.0f;
    }

    const int nkv = (q0 >> 6) + 1;   // causal: tiles 0..q0/64
    const float scale = 0.125f;      // 1/sqrt(64)

    for (int kt = 0; kt < nkv; kt++) {
        const int k0 = kt * 64;
        // Load K and V tiles
#pragma unroll
        for (int it = 0; it < 4; it++) {
            int idx = tid + it * 256;
            int r = idx >> 4;
            int c = (idx & 15) * 4;
            float4 kv = *reinterpret_cast<const float4*>(&Kg[(size_t)(k0 + r) * HD_ + c]);
            *reinterpret_cast<float4*>(&sK[r * FA_S + c]) = kv;
            float4 vv = *reinterpret_cast<const float4*>(&Vg[(size_t)(k0 + r) * HD_ + c]);
            *reinterpret_cast<float4*>(&sV[r * FA_S + c]) = vv;
        }
        __syncthreads();

        // S = Q K^T  (4x4 per thread)
        float s[4][4];
#pragma unroll
        for (int i = 0; i < 4; i++)
#pragma unroll
            for (int j = 0; j < 4; j++) s[i][j] = 0.0f;

#pragma unroll 8
        for (int d = 0; d < 64; d++) {
            float qv[4], kv[4];
#pragma unroll
            for (int i = 0; i < 4; i++) qv[i] = sQ[(4 * ty + i) * FA_S + d];
#pragma unroll
            for (int j = 0; j < 4; j++) kv[j] = sK[(tx + 16 * j) * FA_S + d];
#pragma unroll
            for (int i = 0; i < 4; i++)
#pragma unroll
                for (int j = 0; j < 4; j++)
                    s[i][j] = fmaf(qv[i], kv[j], s[i][j]);
        }

        // scale + causal mask (only diagonal tile can mask)
        const bool diag = (kt == nkv - 1);
#pragma unroll
        for (int i = 0; i < 4; i++) {
            int qg = q0 + 4 * ty + i;
#pragma unroll
            for (int j = 0; j < 4; j++) {
                int kg = k0 + tx + 16 * j;
                s[i][j] = (diag && kg > qg) ? -1e30f : s[i][j] * scale;
            }
        }

        // Online softmax per row (reduce across 16 tx lanes)
        float alpha[4];
#pragma unroll
        for (int i = 0; i < 4; i++) {
            float mx = fmaxf(fmaxf(s[i][0], s[i][1]), fmaxf(s[i][2], s[i][3]));
#pragma unroll
            for (int off = 1; off < 16; off <<= 1)
                mx = fmaxf(mx, __shfl_xor_sync(0xffffffffu, mx, off));
            float mnew = fmaxf(mrow[i], mx);
            alpha[i] = __expf(mrow[i] - mnew);
            mrow[i] = mnew;
            float sum = 0.0f;
#pragma unroll
            for (int j = 0; j < 4; j++) {
                float p = __expf(s[i][j] - mnew);
                s[i][j] = p;
                sum += p;
            }
#pragma unroll
            for (int off = 1; off < 16; off <<= 1)
                sum += __shfl_xor_sync(0xffffffffu, sum, off);
            lrow[i] = lrow[i] * alpha[i] + sum;
#pragma unroll
            for (int j = 0; j < 4; j++) o[i][j] *= alpha[i];
        }

        // Write P to smem for the PV GEMM
#pragma unroll
        for (int i = 0; i < 4; i++)
#pragma unroll
            for (int j = 0; j < 4; j++)
                sP[(4 * ty + i) * FA_S + tx + 16 * j] = s[i][j];
        __syncthreads();

        // O += P @ V
#pragma unroll 8
        for (int jj = 0; jj < 64; jj++) {
            float pv[4], vv[4];
#pragma unroll
            for (int i = 0; i < 4; i++) pv[i] = sP[(4 * ty + i) * FA_S + jj];
#pragma unroll
            for (int j = 0; j < 4; j++) vv[j] = sV[jj * FA_S + tx + 16 * j];
#pragma unroll
            for (int i = 0; i < 4; i++)
#pragma unroll
                for (int j = 0; j < 4; j++)
                    o[i][j] = fmaf(pv[i], vv[j], o[i][j]);
        }
        __syncthreads();   // before next tile overwrites sK/sV/sP
    }

    // Epilogue: normalize and write ctx in [b*T+t][h*HD+hd] layout
    const int b = bh / H_;
    const int h = bh % H_;
#pragma unroll
    for (int i = 0; i < 4; i++) {
        int t = q0 + 4 * ty + i;
        float inv_l = 1.0f / lrow[i];
#pragma unroll
        for (int j = 0; j < 4; j++) {
            int hd = tx + 16 * j;
            g_ctx[((size_t)(b * T_ + t)) * D_ + h * HD_ + hd] = o[i][j] * inv_l;
        }
    }
    (void)gctx;
}

// ---------------------------------------------------------------------------
// Launch
// ---------------------------------------------------------------------------
extern "C" void kernel_launch(void* const* d_in, const int* in_sizes, int n_in,
                              void* d_out, int out_size)
{
    const float* x  = (const float*)d_in[0];
    const float* Wq = (const float*)d_in[1];
    const float* bq = (const float*)d_in[2];
    const float* Wk = (const float*)d_in[3];
    const float* bk = (const float*)d_in[4];
    const float* Wv = (const float*)d_in[5];
    const float* bv = (const float*)d_in[6];
    const float* Wo = (const float*)d_in[7];
    const float* bo = (const float*)d_in[8];
    float* out = (float*)d_out;

    float *qp, *kp, *vp, *cp;
    cudaGetSymbolAddress((void**)&qp, g_q);
    cudaGetSymbolAddress((void**)&kp, g_k);
    cudaGetSymbolAddress((void**)&vp, g_v);
    cudaGetSymbolAddress((void**)&cp, g_ctx);

    dim3 gthr(256);
    dim3 ggrid(D_ / 128, M_ / 128);   // (16, 32)

    gemm_nt<1><<<ggrid, gthr>>>(x, Wq, bq, qp);
    gemm_nt<1><<<ggrid, gthr>>>(x, Wk, bk, kp);
    gemm_nt<1><<<ggrid, gthr>>>(x, Wv, bv, vp);

    const int fa_smem = 4 * 64 * FA_S * (int)sizeof(float);   // 69632 B
    cudaFuncSetAttribute(flash_attn,
                         cudaFuncAttributeMaxDynamicSharedMemorySize, fa_smem);
    dim3 fgrid(T_ / 64, B_ * H_);     // (32, 64)
    flash_attn<<<fgrid, 256, fa_smem>>>(qp, kp, vp, cp);

    gemm_nt<0><<<ggrid, gthr>>>(cp, Wo, bo, out);

    (void)in_sizes; (void)n_in; (void)out_size;
}

// round 6
// speedup vs baseline: 1.9830x; 1.9830x over previous
#include <cuda_runtime.h>
#include <cuda_bf16.h>
#include <stdint.h>
#include <math.h>

#define B_  2
#define T_  2048
#define D_  2048
#define H_  32
#define HD_ 64
#define M_  (B_ * T_)          // 4096 rows for all GEMMs

// ---------------------------------------------------------------------------
// Scratch (device globals — no allocation allowed).  ~151 MB total.
// ---------------------------------------------------------------------------
__device__ float g_q[(size_t)B_ * H_ * T_ * HD_];   // [bh][t][hd]
__device__ float g_k[(size_t)B_ * H_ * T_ * HD_];
__device__ float g_v[(size_t)B_ * H_ * T_ * HD_];

// bf16 hi/lo split operands. X and ctx share g_x*; ONE weight at a time in g_w*.
__device__ __nv_bfloat16 g_xhi[(size_t)M_ * D_];
__device__ __nv_bfloat16 g_xlo[(size_t)M_ * D_];
__device__ __nv_bfloat16 g_whi[(size_t)D_ * D_];
__device__ __nv_bfloat16 g_wlo[(size_t)D_ * D_];

// ---------------------------------------------------------------------------
// PTX helpers (all plain sm_80-era; nothing behind 'a'-gated targets)
// ---------------------------------------------------------------------------
__device__ __forceinline__ uint32_t smem_u32(const void* p) {
    uint32_t a;
    asm("{ .reg .u64 t; cvta.to.shared.u64 t, %1; cvt.u32.u64 %0, t; }"
        : "=r"(a) : "l"(p));
    return a;
}
#define CP_ASYNC16(dst, src) \
    asm volatile("cp.async.cg.shared.global [%0], [%1], 16;" \
                 :: "r"(dst), "l"(src))
#define CP_COMMIT  asm volatile("cp.async.commit_group;" ::: "memory")
#define CP_WAIT(n) asm volatile("cp.async.wait_group %0;" :: "n"(n) : "memory")

__device__ __forceinline__ void ldm_x4(uint32_t (&r)[4], uint32_t addr) {
    asm volatile("ldmatrix.sync.aligned.m8n8.x4.shared.b16 {%0,%1,%2,%3}, [%4];"
                 : "=r"(r[0]), "=r"(r[1]), "=r"(r[2]), "=r"(r[3]) : "r"(addr));
}
__device__ __forceinline__ void mma16816(float (&d)[4], const uint32_t (&a)[4],
                                         uint32_t b0, uint32_t b1) {
    asm volatile(
        "mma.sync.aligned.m16n8k16.row.col.f32.bf16.bf16.f32 "
        "{%0,%1,%2,%3},{%4,%5,%6,%7},{%8,%9},{%0,%1,%2,%3};"
        : "+f"(d[0]), "+f"(d[1]), "+f"(d[2]), "+f"(d[3])
        : "r"(a[0]), "r"(a[1]), "r"(a[2]), "r"(a[3]), "r"(b0), "r"(b1));
}
__device__ __forceinline__ uint32_t pack_bf16x2(__nv_bfloat16 lo, __nv_bfloat16 hi) {
    __nv_bfloat162 v(lo, hi);
    return *reinterpret_cast<uint32_t*>(&v);
}

// ---------------------------------------------------------------------------
// fp32 -> (hi, lo) bf16 split, elementwise. 1 float4 per thread.
// ---------------------------------------------------------------------------
__global__ __launch_bounds__(256) void conv_split(
    const float4* __restrict__ src,
    uint2* __restrict__ hi, uint2* __restrict__ lo, int n4)
{
    int i = blockIdx.x * 256 + threadIdx.x;
    if (i >= n4) return;
    float4 f = src[i];
    __nv_bfloat16 hx = __float2bfloat16_rn(f.x);
    __nv_bfloat16 hy = __float2bfloat16_rn(f.y);
    __nv_bfloat16 hz = __float2bfloat16_rn(f.z);
    __nv_bfloat16 hw = __float2bfloat16_rn(f.w);
    uint2 h, l;
    h.x = pack_bf16x2(hx, hy);
    h.y = pack_bf16x2(hz, hw);
    l.x = pack_bf16x2(__float2bfloat16_rn(f.x - __bfloat162float(hx)),
                      __float2bfloat16_rn(f.y - __bfloat162float(hy)));
    l.y = pack_bf16x2(__float2bfloat16_rn(f.z - __bfloat162float(hz)),
                      __float2bfloat16_rn(f.w - __bfloat162float(hw)));
    hi[i] = h;
    lo[i] = l;
}

// ---------------------------------------------------------------------------
// Tensor-core GEMM via mma.sync (bf16 hi/lo 3-term split):
//   C[m][n] = sum_k A[m][k]*W[n][k] + bias[n]
// CTA 128x128, BK=32, 256 thr (8 warps, 4x2, warp tile 32x64).
// 2-stage cp.async pipeline. SMEM rows stride 40 bf16 (conflict-free ldmatrix).
// ---------------------------------------------------------------------------
#define TILE_B   10240         // bytes per 128x32 tile (stride-40 rows)
#define STAGE_B  40960         // 4 tiles (Ahi, Alo, Whi, Wlo)
#define GSMEM    (2 * STAGE_B) // 81920 B

template <int SPLIT_HEADS>
__global__ __launch_bounds__(256, 2) void gemm_mma(
    const __nv_bfloat16* __restrict__ Ahi,
    const __nv_bfloat16* __restrict__ Alo,
    const __nv_bfloat16* __restrict__ Whi,
    const __nv_bfloat16* __restrict__ Wlo,
    const float* __restrict__ bias,
    float* __restrict__ out)
{
    extern __shared__ __nv_bfloat16 sm[];
    const uint32_t sbase = smem_u32(sm);

    const int tid  = threadIdx.x;
    const int lane = tid & 31;
    const int wid  = tid >> 5;
    const int wm   = wid & 3;       // 0..3 -> 32-row slab
    const int wn   = wid >> 2;      // 0..1 -> 64-col slab
    const int m0   = blockIdx.y * 128;
    const int n0   = blockIdx.x * 128;

    float acc[2][8][4];
#pragma unroll
    for (int mt = 0; mt < 2; mt++)
#pragma unroll
        for (int nt = 0; nt < 8; nt++)
#pragma unroll
            for (int e = 0; e < 4; e++) acc[mt][nt][e] = 0.0f;

    auto load_stage = [&](int s, int k0) {
        const uint32_t st = sbase + (uint32_t)s * STAGE_B;
#pragma unroll
        for (int t8 = 0; t8 < 8; t8++) {
            int c    = tid + t8 * 256;        // 0..2047
            int tile = c >> 9;                // 0..3
            int rem  = c & 511;
            int r    = rem >> 2;              // 0..127
            int kc   = (rem & 3) * 8;         // bf16 offset in row
            uint32_t dst = st + (uint32_t)tile * TILE_B + (uint32_t)(r * 40 + kc) * 2;
            const __nv_bfloat16* g;
            if (tile == 0)      g = Ahi + (size_t)(m0 + r) * 2048 + k0 + kc;
            else if (tile == 1) g = Alo + (size_t)(m0 + r) * 2048 + k0 + kc;
            else if (tile == 2) g = Whi + (size_t)(n0 + r) * 2048 + k0 + kc;
            else                g = Wlo + (size_t)(n0 + r) * 2048 + k0 + kc;
            CP_ASYNC16(dst, g);
        }
    };

    load_stage(0, 0);
    CP_COMMIT;

    const int NIT = 2048 / 32;   // 64

    for (int it = 0; it < NIT; it++) {
        const int s = it & 1;
        if (it + 1 < NIT) {
            load_stage(s ^ 1, (it + 1) * 32);
            CP_COMMIT;
            CP_WAIT(1);
        } else {
            CP_WAIT(0);
        }
        __syncthreads();

        const uint32_t st = sbase + (uint32_t)s * STAGE_B;
#pragma unroll
        for (int ks = 0; ks < 2; ks++) {
            // --- A fragments (hi & lo), 2 m16 tiles per warp ---
            uint32_t aHi[2][4], aLo[2][4];
            const int arow = lane & 15;
            const int akof = ks * 16 + ((lane >> 4) << 3);
#pragma unroll
            for (int mt = 0; mt < 2; mt++) {
                uint32_t ad = st + (uint32_t)((wm * 32 + mt * 16 + arow) * 40 + akof) * 2;
                ldm_x4(aHi[mt], ad);
                ldm_x4(aLo[mt], ad + TILE_B);
            }
            // --- B fragments per n16 group; 3-pass split MMA ---
            const int brow = (lane & 7) + ((lane >> 4) << 3);
            const int bkof = ks * 16 + (((lane >> 3) & 1) << 3);
#pragma unroll
            for (int nt2 = 0; nt2 < 4; nt2++) {
                uint32_t bd = st + 2 * TILE_B +
                    (uint32_t)((wn * 64 + nt2 * 16 + brow) * 40 + bkof) * 2;
                uint32_t bHi[4], bLo[4];
                ldm_x4(bHi, bd);
                ldm_x4(bLo, bd + TILE_B);
#pragma unroll
                for (int mt = 0; mt < 2; mt++) {
                    mma16816(acc[mt][2 * nt2],     aHi[mt], bHi[0], bHi[1]);
                    mma16816(acc[mt][2 * nt2 + 1], aHi[mt], bHi[2], bHi[3]);
                    mma16816(acc[mt][2 * nt2],     aHi[mt], bLo[0], bLo[1]);
                    mma16816(acc[mt][2 * nt2 + 1], aHi[mt], bLo[2], bLo[3]);
                    mma16816(acc[mt][2 * nt2],     aLo[mt], bHi[0], bHi[1]);
                    mma16816(acc[mt][2 * nt2 + 1], aLo[mt], bHi[2], bHi[3]);
                }
            }
        }
        __syncthreads();
    }

    // ---- epilogue: bias + direct global float2 stores ----
    const int gr = lane >> 2;
    const int c2 = (lane & 3) * 2;
#pragma unroll
    for (int mt = 0; mt < 2; mt++) {
#pragma unroll
        for (int nt = 0; nt < 8; nt++) {
            int m = m0 + wm * 32 + mt * 16 + gr;
            int n = n0 + wn * 64 + nt * 8 + c2;
            float b0 = bias[n], b1 = bias[n + 1];
            float2 v0 = make_float2(acc[mt][nt][0] + b0, acc[mt][nt][1] + b1);
            float2 v1 = make_float2(acc[mt][nt][2] + b0, acc[mt][nt][3] + b1);
            if (SPLIT_HEADS) {
                int b  = m >> 11, t = m & (T_ - 1);
                int h  = n >> 6,  hd = n & (HD_ - 1);
                float* p0 = &out[(((size_t)(b * H_ + h)) * T_ + t) * HD_ + hd];
                float* p1 = &out[(((size_t)(b * H_ + h)) * T_ + (t + 8)) * HD_ + hd];
                // m+8 keeps the same batch (tiles are 128-aligned; t+8 in-range)
                *reinterpret_cast<float2*>(p0) = v0;
                *reinterpret_cast<float2*>(p1) = v1;
            } else {
                *reinterpret_cast<float2*>(&out[(size_t)m * D_ + n])       = v0;
                *reinterpret_cast<float2*>(&out[(size_t)(m + 8) * D_ + n]) = v1;
            }
        }
    }
}

// ---------------------------------------------------------------------------
// Flash attention (causal), fp32 compute — identical math to the passing
// Round-1 kernel; epilogue emits the ctx hi/lo bf16 split directly.
// ---------------------------------------------------------------------------
#define FA_S 68

__global__ __launch_bounds__(256, 3) void flash_attn(
    const float* __restrict__ gq,
    const float* __restrict__ gk,
    const float* __restrict__ gv,
    __nv_bfloat16* __restrict__ chi,
    __nv_bfloat16* __restrict__ clo)
{
    extern __shared__ float smem[];
    float* sQ = smem;
    float* sK = sQ + 64 * FA_S;
    float* sV = sK + 64 * FA_S;
    float* sP = sV + 64 * FA_S;

    const int tid = threadIdx.x;
    const int tx  = tid & 15;
    const int ty  = tid >> 4;
    const int bh  = blockIdx.y;
    const int q0  = blockIdx.x * 64;

    const float* Qg = gq + (size_t)bh * T_ * HD_;
    const float* Kg = gk + (size_t)bh * T_ * HD_;
    const float* Vg = gv + (size_t)bh * T_ * HD_;

#pragma unroll
    for (int it = 0; it < 4; it++) {
        int idx = tid + it * 256;
        int r = idx >> 4;
        int c = (idx & 15) * 4;
        float4 v = *reinterpret_cast<const float4*>(&Qg[(size_t)(q0 + r) * HD_ + c]);
        *reinterpret_cast<float4*>(&sQ[r * FA_S + c]) = v;
    }

    float o[4][4];
    float mrow[4], lrow[4];
#pragma unroll
    for (int i = 0; i < 4; i++) {
        mrow[i] = -1e30f; lrow[i] = 0.0f;
#pragma unroll
        for (int j = 0; j < 4; j++) o[i][j] = 0.0f;
    }

    const int nkv = (q0 >> 6) + 1;
    const float scale = 0.125f;

    for (int kt = 0; kt < nkv; kt++) {
        const int k0 = kt * 64;
#pragma unroll
        for (int it = 0; it < 4; it++) {
            int idx = tid + it * 256;
            int r = idx >> 4;
            int c = (idx & 15) * 4;
            float4 kv = *reinterpret_cast<const float4*>(&Kg[(size_t)(k0 + r) * HD_ + c]);
            *reinterpret_cast<float4*>(&sK[r * FA_S + c]) = kv;
            float4 vv = *reinterpret_cast<const float4*>(&Vg[(size_t)(k0 + r) * HD_ + c]);
            *reinterpret_cast<float4*>(&sV[r * FA_S + c]) = vv;
        }
        __syncthreads();

        float s[4][4];
#pragma unroll
        for (int i = 0; i < 4; i++)
#pragma unroll
            for (int j = 0; j < 4; j++) s[i][j] = 0.0f;

#pragma unroll 8
        for (int d = 0; d < 64; d++) {
            float qv[4], kv[4];
#pragma unroll
            for (int i = 0; i < 4; i++) qv[i] = sQ[(4 * ty + i) * FA_S + d];
#pragma unroll
            for (int j = 0; j < 4; j++) kv[j] = sK[(tx + 16 * j) * FA_S + d];
#pragma unroll
            for (int i = 0; i < 4; i++)
#pragma unroll
                for (int j = 0; j < 4; j++)
                    s[i][j] = fmaf(qv[i], kv[j], s[i][j]);
        }

        const bool diag = (kt == nkv - 1);
#pragma unroll
        for (int i = 0; i < 4; i++) {
            int qg = q0 + 4 * ty + i;
#pragma unroll
            for (int j = 0; j < 4; j++) {
                int kg = k0 + tx + 16 * j;
                s[i][j] = (diag && kg > qg) ? -1e30f : s[i][j] * scale;
            }
        }

        float alpha[4];
#pragma unroll
        for (int i = 0; i < 4; i++) {
            float mx = fmaxf(fmaxf(s[i][0], s[i][1]), fmaxf(s[i][2], s[i][3]));
#pragma unroll
            for (int off = 1; off < 16; off <<= 1)
                mx = fmaxf(mx, __shfl_xor_sync(0xffffffffu, mx, off));
            float mnew = fmaxf(mrow[i], mx);
            alpha[i] = __expf(mrow[i] - mnew);
            mrow[i] = mnew;
            float sum = 0.0f;
#pragma unroll
            for (int j = 0; j < 4; j++) {
                float p = __expf(s[i][j] - mnew);
                s[i][j] = p;
                sum += p;
            }
#pragma unroll
            for (int off = 1; off < 16; off <<= 1)
                sum += __shfl_xor_sync(0xffffffffu, sum, off);
            lrow[i] = lrow[i] * alpha[i] + sum;
#pragma unroll
            for (int j = 0; j < 4; j++) o[i][j] *= alpha[i];
        }

#pragma unroll
        for (int i = 0; i < 4; i++)
#pragma unroll
            for (int j = 0; j < 4; j++)
                sP[(4 * ty + i) * FA_S + tx + 16 * j] = s[i][j];
        __syncthreads();

#pragma unroll 8
        for (int jj = 0; jj < 64; jj++) {
            float pv[4], vv[4];
#pragma unroll
            for (int i = 0; i < 4; i++) pv[i] = sP[(4 * ty + i) * FA_S + jj];
#pragma unroll
            for (int j = 0; j < 4; j++) vv[j] = sV[jj * FA_S + tx + 16 * j];
#pragma unroll
            for (int i = 0; i < 4; i++)
#pragma unroll
                for (int j = 0; j < 4; j++)
                    o[i][j] = fmaf(pv[i], vv[j], o[i][j]);
        }
        __syncthreads();
    }

    // Epilogue: normalize and emit ctx hi/lo bf16 split in [b*T+t][h*HD+hd]
    const int b = bh / H_;
    const int h = bh % H_;
#pragma unroll
    for (int i = 0; i < 4; i++) {
        int t = q0 + 4 * ty + i;
        float inv_l = 1.0f / lrow[i];
        size_t rowbase = ((size_t)(b * T_ + t)) * D_ + h * HD_;
#pragma unroll
        for (int j = 0; j < 4; j++) {
            int hd = tx + 16 * j;
            float v = o[i][j] * inv_l;
            __nv_bfloat16 vh = __float2bfloat16_rn(v);
            chi[rowbase + hd] = vh;
            clo[rowbase + hd] = __float2bfloat16_rn(v - __bfloat162float(vh));
        }
    }
}

// ---------------------------------------------------------------------------
// Launch: conv X; then per weight {conv W; gemm}; flash; conv-free O path.
// ---------------------------------------------------------------------------
extern "C" void kernel_launch(void* const* d_in, const int* in_sizes, int n_in,
                              void* d_out, int out_size)
{
    const float* x  = (const float*)d_in[0];
    const float* Wq = (const float*)d_in[1];
    const float* bq = (const float*)d_in[2];
    const float* Wk = (const float*)d_in[3];
    const float* bk = (const float*)d_in[4];
    const float* Wv = (const float*)d_in[5];
    const float* bv = (const float*)d_in[6];
    const float* Wo = (const float*)d_in[7];
    const float* bo = (const float*)d_in[8];
    float* out = (float*)d_out;

    float *qp, *kp, *vp;
    __nv_bfloat16 *xhi, *xlo, *whi, *wlo;
    cudaGetSymbolAddress((void**)&qp,  g_q);
    cudaGetSymbolAddress((void**)&kp,  g_k);
    cudaGetSymbolAddress((void**)&vp,  g_v);
    cudaGetSymbolAddress((void**)&xhi, g_xhi);
    cudaGetSymbolAddress((void**)&xlo, g_xlo);
    cudaGetSymbolAddress((void**)&whi, g_whi);
    cudaGetSymbolAddress((void**)&wlo, g_wlo);

    cudaFuncSetAttribute(gemm_mma<1>,
                         cudaFuncAttributeMaxDynamicSharedMemorySize, GSMEM);
    cudaFuncSetAttribute(gemm_mma<0>,
                         cudaFuncAttributeMaxDynamicSharedMemorySize, GSMEM);
    const int fa_smem = 4 * 64 * FA_S * (int)sizeof(float);   // 69632 B
    cudaFuncSetAttribute(flash_attn,
                         cudaFuncAttributeMaxDynamicSharedMemorySize, fa_smem);

    const int n4x = (int)((size_t)M_ * D_ / 4);   // 2,097,152
    const int n4w = (int)((size_t)D_ * D_ / 4);   // 1,048,576
    dim3 gthr(256);
    dim3 ggrid(D_ / 128, M_ / 128);               // (16, 32)
    dim3 fgrid(T_ / 64, B_ * H_);                 // (32, 64)

    // X -> hi/lo split
    conv_split<<<(n4x + 255) / 256, 256>>>(
        (const float4*)x, (uint2*)xhi, (uint2*)xlo, n4x);

    // Q projection
    conv_split<<<(n4w + 255) / 256, 256>>>(
        (const float4*)Wq, (uint2*)whi, (uint2*)wlo, n4w);
    gemm_mma<1><<<ggrid, gthr, GSMEM>>>(xhi, xlo, whi, wlo, bq, qp);

    // K projection
    conv_split<<<(n4w + 255) / 256, 256>>>(
        (const float4*)Wk, (uint2*)whi, (uint2*)wlo, n4w);
    gemm_mma<1><<<ggrid, gthr, GSMEM>>>(xhi, xlo, whi, wlo, bk, kp);

    // V projection
    conv_split<<<(n4w + 255) / 256, 256>>>(
        (const float4*)Wv, (uint2*)whi, (uint2*)wlo, n4w);
    gemm_mma<1><<<ggrid, gthr, GSMEM>>>(xhi, xlo, whi, wlo, bv, vp);

    // Attention: writes ctx hi/lo split directly into X's buffers
    flash_attn<<<fgrid, 256, fa_smem>>>(qp, kp, vp, xhi, xlo);

    // O projection
    conv_split<<<(n4w + 255) / 256, 256>>>(
        (const float4*)Wo, (uint2*)whi, (uint2*)wlo, n4w);
    gemm_mma<0><<<ggrid, gthr, GSMEM>>>(xhi, xlo, whi, wlo, bo, out);

    (void)in_sizes; (void)n_in; (void)out_size;
}

// round 7
// speedup vs baseline: 2.9828x; 1.5042x over previous
#include <cuda_runtime.h>
#include <cuda_bf16.h>
#include <stdint.h>
#include <math.h>

#define B_  2
#define T_  2048
#define D_  2048
#define H_  32
#define HD_ 64
#define M_  (B_ * T_)          // 4096 rows for all GEMMs

// ---------------------------------------------------------------------------
// Scratch (device globals — no allocation allowed). ~144 MB total.
// ---------------------------------------------------------------------------
__device__ __nv_bfloat16 g_qhi[(size_t)M_ * D_];   // [bh][t][hd] head-split
__device__ __nv_bfloat16 g_qlo[(size_t)M_ * D_];
__device__ __nv_bfloat16 g_khi[(size_t)M_ * D_];
__device__ __nv_bfloat16 g_klo[(size_t)M_ * D_];
__device__ __nv_bfloat16 g_vhi[(size_t)M_ * D_];
__device__ __nv_bfloat16 g_vlo[(size_t)M_ * D_];
__device__ __nv_bfloat16 g_xhi[(size_t)M_ * D_];   // X, later ctx
__device__ __nv_bfloat16 g_xlo[(size_t)M_ * D_];
__device__ __nv_bfloat16 g_whi[(size_t)D_ * D_];   // one weight at a time
__device__ __nv_bfloat16 g_wlo[(size_t)D_ * D_];

// ---------------------------------------------------------------------------
// PTX helpers (plain sm_80-era; nothing 'a'-gated)
// ---------------------------------------------------------------------------
__device__ __forceinline__ uint32_t smem_u32(const void* p) {
    uint32_t a;
    asm("{ .reg .u64 t; cvta.to.shared.u64 t, %1; cvt.u32.u64 %0, t; }"
        : "=r"(a) : "l"(p));
    return a;
}
#define CP_ASYNC16(dst, src) \
    asm volatile("cp.async.cg.shared.global [%0], [%1], 16;" \
                 :: "r"(dst), "l"(src))
#define CP_COMMIT  asm volatile("cp.async.commit_group;" ::: "memory")
#define CP_WAIT(n) asm volatile("cp.async.wait_group %0;" :: "n"(n) : "memory")

__device__ __forceinline__ void ldm_x4(uint32_t (&r)[4], uint32_t addr) {
    asm volatile("ldmatrix.sync.aligned.m8n8.x4.shared.b16 {%0,%1,%2,%3}, [%4];"
                 : "=r"(r[0]), "=r"(r[1]), "=r"(r[2]), "=r"(r[3]) : "r"(addr));
}
__device__ __forceinline__ void ldm_x4_t(uint32_t (&r)[4], uint32_t addr) {
    asm volatile("ldmatrix.sync.aligned.m8n8.x4.trans.shared.b16 {%0,%1,%2,%3}, [%4];"
                 : "=r"(r[0]), "=r"(r[1]), "=r"(r[2]), "=r"(r[3]) : "r"(addr));
}
__device__ __forceinline__ void mma16816(float (&d)[4], const uint32_t (&a)[4],
                                         uint32_t b0, uint32_t b1) {
    asm volatile(
        "mma.sync.aligned.m16n8k16.row.col.f32.bf16.bf16.f32 "
        "{%0,%1,%2,%3},{%4,%5,%6,%7},{%8,%9},{%0,%1,%2,%3};"
        : "+f"(d[0]), "+f"(d[1]), "+f"(d[2]), "+f"(d[3])
        : "r"(a[0]), "r"(a[1]), "r"(a[2]), "r"(a[3]), "r"(b0), "r"(b1));
}
__device__ __forceinline__ uint32_t pack_bf16x2(__nv_bfloat16 lo, __nv_bfloat16 hi) {
    __nv_bfloat162 v(lo, hi);
    return *reinterpret_cast<uint32_t*>(&v);
}
// split a float pair into packed hi bf16x2 and residual lo bf16x2
__device__ __forceinline__ void split2(float a, float b, uint32_t& hi, uint32_t& lo) {
    __nv_bfloat16 ha = __float2bfloat16_rn(a);
    __nv_bfloat16 hb = __float2bfloat16_rn(b);
    hi = pack_bf16x2(ha, hb);
    lo = pack_bf16x2(__float2bfloat16_rn(a - __bfloat162float(ha)),
                     __float2bfloat16_rn(b - __bfloat162float(hb)));
}

// ---------------------------------------------------------------------------
// fp32 -> (hi, lo) bf16 split, elementwise. 1 float4 per thread.
// ---------------------------------------------------------------------------
__global__ __launch_bounds__(256) void conv_split(
    const float4* __restrict__ src,
    uint2* __restrict__ hi, uint2* __restrict__ lo, int n4)
{
    int i = blockIdx.x * 256 + threadIdx.x;
    if (i >= n4) return;
    float4 f = src[i];
    uint2 h, l;
    split2(f.x, f.y, h.x, l.x);
    split2(f.z, f.w, h.y, l.y);
    hi[i] = h;
    lo[i] = l;
}

// ---------------------------------------------------------------------------
// Tensor-core GEMM via mma.sync (bf16 hi/lo 3-term split):
//   C[m][n] = sum_k A[m][k]*W[n][k] + bias[n]
// CTA 128x128, BK=32, 256 thr (8 warps, 4x2, warp tile 32x64).
// MODE 0: fp32 [m][n] to outf.  MODE 1: head-split bf16 hi/lo to outh/outl.
// ---------------------------------------------------------------------------
#define TILE_B   10240         // bytes per 128x32 tile (stride-40 rows)
#define STAGE_B  40960
#define GSMEM    (2 * STAGE_B) // 81920 B

template <int MODE>
__global__ __launch_bounds__(256, 2) void gemm_mma(
    const __nv_bfloat16* __restrict__ Ahi,
    const __nv_bfloat16* __restrict__ Alo,
    const __nv_bfloat16* __restrict__ Whi,
    const __nv_bfloat16* __restrict__ Wlo,
    const float* __restrict__ bias,
    float* __restrict__ outf,
    __nv_bfloat16* __restrict__ outh,
    __nv_bfloat16* __restrict__ outl)
{
    extern __shared__ __nv_bfloat16 sm[];
    const uint32_t sbase = smem_u32(sm);

    const int tid  = threadIdx.x;
    const int lane = tid & 31;
    const int wid  = tid >> 5;
    const int wm   = wid & 3;
    const int wn   = wid >> 2;
    const int m0   = blockIdx.y * 128;
    const int n0   = blockIdx.x * 128;

    float acc[2][8][4];
#pragma unroll
    for (int mt = 0; mt < 2; mt++)
#pragma unroll
        for (int nt = 0; nt < 8; nt++)
#pragma unroll
            for (int e = 0; e < 4; e++) acc[mt][nt][e] = 0.0f;

    auto load_stage = [&](int s, int k0) {
        const uint32_t st = sbase + (uint32_t)s * STAGE_B;
#pragma unroll
        for (int t8 = 0; t8 < 8; t8++) {
            int c    = tid + t8 * 256;
            int tile = c >> 9;
            int rem  = c & 511;
            int r    = rem >> 2;
            int kc   = (rem & 3) * 8;
            uint32_t dst = st + (uint32_t)tile * TILE_B + (uint32_t)(r * 40 + kc) * 2;
            const __nv_bfloat16* g;
            if (tile == 0)      g = Ahi + (size_t)(m0 + r) * 2048 + k0 + kc;
            else if (tile == 1) g = Alo + (size_t)(m0 + r) * 2048 + k0 + kc;
            else if (tile == 2) g = Whi + (size_t)(n0 + r) * 2048 + k0 + kc;
            else                g = Wlo + (size_t)(n0 + r) * 2048 + k0 + kc;
            CP_ASYNC16(dst, g);
        }
    };

    load_stage(0, 0);
    CP_COMMIT;

    const int NIT = 2048 / 32;

    for (int it = 0; it < NIT; it++) {
        const int s = it & 1;
        if (it + 1 < NIT) {
            load_stage(s ^ 1, (it + 1) * 32);
            CP_COMMIT;
            CP_WAIT(1);
        } else {
            CP_WAIT(0);
        }
        __syncthreads();

        const uint32_t st = sbase + (uint32_t)s * STAGE_B;
#pragma unroll
        for (int ks = 0; ks < 2; ks++) {
            uint32_t aHi[2][4], aLo[2][4];
            const int arow = lane & 15;
            const int akof = ks * 16 + ((lane >> 4) << 3);
#pragma unroll
            for (int mt = 0; mt < 2; mt++) {
                uint32_t ad = st + (uint32_t)((wm * 32 + mt * 16 + arow) * 40 + akof) * 2;
                ldm_x4(aHi[mt], ad);
                ldm_x4(aLo[mt], ad + TILE_B);
            }
            const int brow = (lane & 7) + ((lane >> 4) << 3);
            const int bkof = ks * 16 + (((lane >> 3) & 1) << 3);
#pragma unroll
            for (int nt2 = 0; nt2 < 4; nt2++) {
                uint32_t bd = st + 2 * TILE_B +
                    (uint32_t)((wn * 64 + nt2 * 16 + brow) * 40 + bkof) * 2;
                uint32_t bHi[4], bLo[4];
                ldm_x4(bHi, bd);
                ldm_x4(bLo, bd + TILE_B);
#pragma unroll
                for (int mt = 0; mt < 2; mt++) {
                    mma16816(acc[mt][2 * nt2],     aHi[mt], bHi[0], bHi[1]);
                    mma16816(acc[mt][2 * nt2 + 1], aHi[mt], bHi[2], bHi[3]);
                    mma16816(acc[mt][2 * nt2],     aHi[mt], bLo[0], bLo[1]);
                    mma16816(acc[mt][2 * nt2 + 1], aHi[mt], bLo[2], bLo[3]);
                    mma16816(acc[mt][2 * nt2],     aLo[mt], bHi[0], bHi[1]);
                    mma16816(acc[mt][2 * nt2 + 1], aLo[mt], bHi[2], bHi[3]);
                }
            }
        }
        __syncthreads();
    }

    // ---- epilogue ----
    const int gr = lane >> 2;
    const int c2 = (lane & 3) * 2;
#pragma unroll
    for (int mt = 0; mt < 2; mt++) {
#pragma unroll
        for (int nt = 0; nt < 8; nt++) {
            int m = m0 + wm * 32 + mt * 16 + gr;
            int n = n0 + wn * 64 + nt * 8 + c2;
            float b0 = bias[n], b1 = bias[n + 1];
            float f00 = acc[mt][nt][0] + b0, f01 = acc[mt][nt][1] + b1;
            float f10 = acc[mt][nt][2] + b0, f11 = acc[mt][nt][3] + b1;
            if (MODE == 1) {
                int b  = m >> 11, t = m & (T_ - 1);
                int h  = n >> 6,  hd = n & (HD_ - 1);
                size_t i0 = (((size_t)(b * H_ + h)) * T_ + t) * HD_ + hd;
                size_t i1 = (((size_t)(b * H_ + h)) * T_ + (t + 8)) * HD_ + hd;
                uint32_t hi0, lo0, hi1, lo1;
                split2(f00, f01, hi0, lo0);
                split2(f10, f11, hi1, lo1);
                *reinterpret_cast<uint32_t*>(&outh[i0]) = hi0;
                *reinterpret_cast<uint32_t*>(&outl[i0]) = lo0;
                *reinterpret_cast<uint32_t*>(&outh[i1]) = hi1;
                *reinterpret_cast<uint32_t*>(&outl[i1]) = lo1;
            } else {
                *reinterpret_cast<float2*>(&outf[(size_t)m * D_ + n])
                    = make_float2(f00, f01);
                *reinterpret_cast<float2*>(&outf[(size_t)(m + 8) * D_ + n])
                    = make_float2(f10, f11);
            }
        }
    }
}

// ---------------------------------------------------------------------------
// Flash attention (causal) on tensor cores — FA2-style.
// Grid (32, 64), 128 thr (4 warps). Br=Bc=64, HD=64.
// 3-term QK^T, online softmax in fragments, register P->A-frag pack,
// 3-term PV with ldmatrix.trans V. Writes ctx hi/lo split.
// ---------------------------------------------------------------------------
#define FS        72                      // smem row stride (bf16)
#define FKTILE_B  (64 * FS * 2)           // 9216 B per 64x64 tile
#define FQ_B      (2 * FKTILE_B)          // Qhi, Qlo
#define FSTG_B    (4 * FKTILE_B)          // Khi, Klo, Vhi, Vlo
#define FSMEM     (FQ_B + 2 * FSTG_B)     // 92160 B

__global__ __launch_bounds__(128, 2) void flash_mma(
    const __nv_bfloat16* __restrict__ qhi_g, const __nv_bfloat16* __restrict__ qlo_g,
    const __nv_bfloat16* __restrict__ khi_g, const __nv_bfloat16* __restrict__ klo_g,
    const __nv_bfloat16* __restrict__ vhi_g, const __nv_bfloat16* __restrict__ vlo_g,
    __nv_bfloat16* __restrict__ chi, __nv_bfloat16* __restrict__ clo)
{
    extern __shared__ char fsm[];
    const uint32_t sb = smem_u32(fsm);
    const int tid  = threadIdx.x;
    const int lane = tid & 31;
    const int w    = tid >> 5;
    const int bh   = blockIdx.y;
    const int q0   = (gridDim.x - 1 - blockIdx.x) * 64;   // heavy tiles first
    const size_t hb = (size_t)bh * T_ * HD_;

    // ---- async load Q (hi+lo) ----
#pragma unroll
    for (int m = 0; m < 2; m++) {
        const __nv_bfloat16* src = m ? qlo_g : qhi_g;
        uint32_t dstb = sb + (uint32_t)m * FKTILE_B;
#pragma unroll
        for (int i = 0; i < 4; i++) {
            int c = tid + i * 128;          // 0..511
            int r = c >> 3, ch = (c & 7) * 8;
            CP_ASYNC16(dstb + (uint32_t)(r * FS + ch) * 2,
                       src + hb + (size_t)(q0 + r) * HD_ + ch);
        }
    }
    CP_COMMIT;

    auto load_kv = [&](int s, int k0) {
        uint32_t st = sb + FQ_B + (uint32_t)s * FSTG_B;
        const __nv_bfloat16* srcs[4] = {khi_g, klo_g, vhi_g, vlo_g};
#pragma unroll
        for (int m = 0; m < 4; m++) {
#pragma unroll
            for (int i = 0; i < 4; i++) {
                int c = tid + i * 128;
                int r = c >> 3, ch = (c & 7) * 8;
                CP_ASYNC16(st + (uint32_t)m * FKTILE_B + (uint32_t)(r * FS + ch) * 2,
                           srcs[m] + hb + (size_t)(k0 + r) * HD_ + ch);
            }
        }
    };
    load_kv(0, 0);
    CP_COMMIT;
    CP_WAIT(1);            // Q done (KV0 may be pending)
    __syncthreads();

    // ---- Q fragments (register-resident for the whole kernel) ----
    uint32_t qh[4][4], ql[4][4];
    {
        int arow = lane & 15, akof = (lane >> 4) * 8;
#pragma unroll
        for (int kt = 0; kt < 4; kt++) {
            uint32_t ad = sb + (uint32_t)((16 * w + arow) * FS + kt * 16 + akof) * 2;
            ldm_x4(qh[kt], ad);
            ldm_x4(ql[kt], ad + FKTILE_B);
        }
    }

    float ctx[8][4];
#pragma unroll
    for (int nt = 0; nt < 8; nt++)
#pragma unroll
        for (int e = 0; e < 4; e++) ctx[nt][e] = 0.0f;
    float mrow0 = -1e30f, mrow1 = -1e30f, lrow0 = 0.0f, lrow1 = 0.0f;

    const int nkv = (q0 >> 6) + 1;
    const int gr  = lane >> 2;
    const int c2  = (lane & 3) * 2;
    const float scale = 0.125f;
    const int qg0 = q0 + 16 * w + gr;     // row of e=0,1
    const int qg1 = qg0 + 8;              // row of e=2,3

    for (int kt = 0; kt < nkv; kt++) {
        const int s = kt & 1;
        if (kt + 1 < nkv) {
            load_kv(s ^ 1, (kt + 1) * 64);
            CP_COMMIT;
            CP_WAIT(1);
        } else {
            CP_WAIT(0);
        }
        __syncthreads();
        const uint32_t st = sb + FQ_B + (uint32_t)s * FSTG_B;

        // ---- S = Q K^T (3-term) ----
        float sa[8][4];
#pragma unroll
        for (int nt = 0; nt < 8; nt++)
#pragma unroll
            for (int e = 0; e < 4; e++) sa[nt][e] = 0.0f;
        {
            const int brow = (lane & 7) + ((lane >> 4) << 3);
            const int bkof = ((lane >> 3) & 1) << 3;
#pragma unroll
            for (int k4 = 0; k4 < 4; k4++) {
#pragma unroll
                for (int nt2 = 0; nt2 < 4; nt2++) {
                    uint32_t bd = st +
                        (uint32_t)((nt2 * 16 + brow) * FS + k4 * 16 + bkof) * 2;
                    uint32_t bh4[4], bl4[4];
                    ldm_x4(bh4, bd);
                    ldm_x4(bl4, bd + FKTILE_B);
                    mma16816(sa[2 * nt2],     qh[k4], bh4[0], bh4[1]);
                    mma16816(sa[2 * nt2 + 1], qh[k4], bh4[2], bh4[3]);
                    mma16816(sa[2 * nt2],     qh[k4], bl4[0], bl4[1]);
                    mma16816(sa[2 * nt2 + 1], qh[k4], bl4[2], bl4[3]);
                    mma16816(sa[2 * nt2],     ql[k4], bh4[0], bh4[1]);
                    mma16816(sa[2 * nt2 + 1], ql[k4], bh4[2], bh4[3]);
                }
            }
        }

        // ---- scale + causal mask (diag tile only) ----
        const bool diag = (kt == nkv - 1);
#pragma unroll
        for (int nt = 0; nt < 8; nt++) {
            int kg = kt * 64 + nt * 8 + c2;
            sa[nt][0] = (diag && kg     > qg0) ? -1e30f : sa[nt][0] * scale;
            sa[nt][1] = (diag && kg + 1 > qg0) ? -1e30f : sa[nt][1] * scale;
            sa[nt][2] = (diag && kg     > qg1) ? -1e30f : sa[nt][2] * scale;
            sa[nt][3] = (diag && kg + 1 > qg1) ? -1e30f : sa[nt][3] * scale;
        }

        // ---- online softmax ----
        float mx0 = -1e30f, mx1 = -1e30f;
#pragma unroll
        for (int nt = 0; nt < 8; nt++) {
            mx0 = fmaxf(mx0, fmaxf(sa[nt][0], sa[nt][1]));
            mx1 = fmaxf(mx1, fmaxf(sa[nt][2], sa[nt][3]));
        }
        mx0 = fmaxf(mx0, __shfl_xor_sync(0xffffffffu, mx0, 1));
        mx0 = fmaxf(mx0, __shfl_xor_sync(0xffffffffu, mx0, 2));
        mx1 = fmaxf(mx1, __shfl_xor_sync(0xffffffffu, mx1, 1));
        mx1 = fmaxf(mx1, __shfl_xor_sync(0xffffffffu, mx1, 2));
        float mn0 = fmaxf(mrow0, mx0), mn1 = fmaxf(mrow1, mx1);
        float al0 = __expf(mrow0 - mn0), al1 = __expf(mrow1 - mn1);
        mrow0 = mn0; mrow1 = mn1;
        float sum0 = 0.0f, sum1 = 0.0f;
#pragma unroll
        for (int nt = 0; nt < 8; nt++) {
            float p0 = __expf(sa[nt][0] - mn0);
            float p1 = __expf(sa[nt][1] - mn0);
            float p2 = __expf(sa[nt][2] - mn1);
            float p3 = __expf(sa[nt][3] - mn1);
            sa[nt][0] = p0; sa[nt][1] = p1; sa[nt][2] = p2; sa[nt][3] = p3;
            sum0 += p0 + p1; sum1 += p2 + p3;
        }
        sum0 += __shfl_xor_sync(0xffffffffu, sum0, 1);
        sum0 += __shfl_xor_sync(0xffffffffu, sum0, 2);
        sum1 += __shfl_xor_sync(0xffffffffu, sum1, 1);
        sum1 += __shfl_xor_sync(0xffffffffu, sum1, 2);
        lrow0 = lrow0 * al0 + sum0;
        lrow1 = lrow1 * al1 + sum1;
#pragma unroll
        for (int nt = 0; nt < 8; nt++) {
            ctx[nt][0] *= al0; ctx[nt][1] *= al0;
            ctx[nt][2] *= al1; ctx[nt][3] *= al1;
        }

        // ---- ctx += P V (3-term), interleaved per k16 tile ----
        {
            const int vrow = (lane & 7) + (((lane >> 3) & 1) << 3);
            const int vcol = (lane >> 4) << 3;
#pragma unroll
            for (int kt2 = 0; kt2 < 4; kt2++) {
                uint32_t pa[4], pb[4];   // P hi / lo A-frags
                split2(sa[2 * kt2][0],     sa[2 * kt2][1],     pa[0], pb[0]);
                split2(sa[2 * kt2][2],     sa[2 * kt2][3],     pa[1], pb[1]);
                split2(sa[2 * kt2 + 1][0], sa[2 * kt2 + 1][1], pa[2], pb[2]);
                split2(sa[2 * kt2 + 1][2], sa[2 * kt2 + 1][3], pa[3], pb[3]);
#pragma unroll
                for (int dt = 0; dt < 4; dt++) {
                    uint32_t vd = st + 2 * FKTILE_B +
                        (uint32_t)((16 * kt2 + vrow) * FS + dt * 16 + vcol) * 2;
                    uint32_t vh4[4], vl4[4];
                    ldm_x4_t(vh4, vd);
                    ldm_x4_t(vl4, vd + FKTILE_B);
                    mma16816(ctx[2 * dt],     pa, vh4[0], vh4[1]);
                    mma16816(ctx[2 * dt + 1], pa, vh4[2], vh4[3]);
                    mma16816(ctx[2 * dt],     pa, vl4[0], vl4[1]);
                    mma16816(ctx[2 * dt + 1], pa, vl4[2], vl4[3]);
                    mma16816(ctx[2 * dt],     pb, vh4[0], vh4[1]);
                    mma16816(ctx[2 * dt + 1], pb, vh4[2], vh4[3]);
                }
            }
        }
        __syncthreads();   // before next prefetch overwrites this stage
    }

    // ---- epilogue: normalize, emit ctx hi/lo split [b*T+t][h*HD+hd] ----
    const float il0 = 1.0f / lrow0, il1 = 1.0f / lrow1;
    const int b = bh / H_, h = bh % H_;
    const int t0 = q0 + 16 * w + gr, t1 = t0 + 8;
#pragma unroll
    for (int nt = 0; nt < 8; nt++) {
        int d = nt * 8 + c2;
        size_t i0 = ((size_t)(b * T_ + t0)) * D_ + h * HD_ + d;
        size_t i1 = ((size_t)(b * T_ + t1)) * D_ + h * HD_ + d;
        uint32_t hi0, lo0, hi1, lo1;
        split2(ctx[nt][0] * il0, ctx[nt][1] * il0, hi0, lo0);
        split2(ctx[nt][2] * il1, ctx[nt][3] * il1, hi1, lo1);
        *reinterpret_cast<uint32_t*>(&chi[i0]) = hi0;
        *reinterpret_cast<uint32_t*>(&clo[i0]) = lo0;
        *reinterpret_cast<uint32_t*>(&chi[i1]) = hi1;
        *reinterpret_cast<uint32_t*>(&clo[i1]) = lo1;
    }
}

// ---------------------------------------------------------------------------
// Launch
// ---------------------------------------------------------------------------
extern "C" void kernel_launch(void* const* d_in, const int* in_sizes, int n_in,
                              void* d_out, int out_size)
{
    const float* x  = (const float*)d_in[0];
    const float* Wq = (const float*)d_in[1];
    const float* bq = (const float*)d_in[2];
    const float* Wk = (const float*)d_in[3];
    const float* bk = (const float*)d_in[4];
    const float* Wv = (const float*)d_in[5];
    const float* bv = (const float*)d_in[6];
    const float* Wo = (const float*)d_in[7];
    const float* bo = (const float*)d_in[8];
    float* out = (float*)d_out;

    __nv_bfloat16 *qhi, *qlo, *khi, *klo, *vhi, *vlo, *xhi, *xlo, *whi, *wlo;
    cudaGetSymbolAddress((void**)&qhi, g_qhi);
    cudaGetSymbolAddress((void**)&qlo, g_qlo);
    cudaGetSymbolAddress((void**)&khi, g_khi);
    cudaGetSymbolAddress((void**)&klo, g_klo);
    cudaGetSymbolAddress((void**)&vhi, g_vhi);
    cudaGetSymbolAddress((void**)&vlo, g_vlo);
    cudaGetSymbolAddress((void**)&xhi, g_xhi);
    cudaGetSymbolAddress((void**)&xlo, g_xlo);
    cudaGetSymbolAddress((void**)&whi, g_whi);
    cudaGetSymbolAddress((void**)&wlo, g_wlo);

    cudaFuncSetAttribute(gemm_mma<1>,
                         cudaFuncAttributeMaxDynamicSharedMemorySize, GSMEM);
    cudaFuncSetAttribute(gemm_mma<0>,
                         cudaFuncAttributeMaxDynamicSharedMemorySize, GSMEM);
    cudaFuncSetAttribute(flash_mma,
                         cudaFuncAttributeMaxDynamicSharedMemorySize, FSMEM);

    const int n4x = (int)((size_t)M_ * D_ / 4);
    const int n4w = (int)((size_t)D_ * D_ / 4);
    dim3 gthr(256);
    dim3 ggrid(D_ / 128, M_ / 128);   // (16, 32)
    dim3 fgrid(T_ / 64, B_ * H_);     // (32, 64)

    // X -> hi/lo split
    conv_split<<<(n4x + 255) / 256, 256>>>(
        (const float4*)x, (uint2*)xhi, (uint2*)xlo, n4x);

    // Q/K/V projections (bf16 hi/lo head-split outputs)
    conv_split<<<(n4w + 255) / 256, 256>>>(
        (const float4*)Wq, (uint2*)whi, (uint2*)wlo, n4w);
    gemm_mma<1><<<ggrid, gthr, GSMEM>>>(xhi, xlo, whi, wlo, bq, nullptr, qhi, qlo);

    conv_split<<<(n4w + 255) / 256, 256>>>(
        (const float4*)Wk, (uint2*)whi, (uint2*)wlo, n4w);
    gemm_mma<1><<<ggrid, gthr, GSMEM>>>(xhi, xlo, whi, wlo, bk, nullptr, khi, klo);

    conv_split<<<(n4w + 255) / 256, 256>>>(
        (const float4*)Wv, (uint2*)whi, (uint2*)wlo, n4w);
    gemm_mma<1><<<ggrid, gthr, GSMEM>>>(xhi, xlo, whi, wlo, bv, nullptr, vhi, vlo);

    // Flash attention on tensor cores; ctx hi/lo into X's buffers
    flash_mma<<<fgrid, 128, FSMEM>>>(qhi, qlo, khi, klo, vhi, vlo, xhi, xlo);

    // O projection (fp32 output)
    conv_split<<<(n4w + 255) / 256, 256>>>(
        (const float4*)Wo, (uint2*)whi, (uint2*)wlo, n4w);
    gemm_mma<0><<<ggrid, gthr, GSMEM>>>(xhi, xlo, whi, wlo, bo, out, nullptr, nullptr);

    (void)in_sizes; (void)n_in; (void)out_size;
}